// round 14
// baseline (speedup 1.0000x reference)
#include <cuda_runtime.h>
#include <cstdint>

// Problem constants
constexpr int NB = 16;
constexpr int NC = 128;
constexpr int NH = 64;
constexpr int NW = 64;
constexpr int HW = NH * NW;
constexpr int NOC = 128;

// Scratch (allocation-free rule: __device__ globals)
__device__ float g_T[NB * 2 * HW];        // per-parity channel sums
__device__ float g_avg[NB * 2 * HW];      // 3x3 box mean / 576
__device__ float g_W2[NOC * 2];           // sum of weights per (o, parity)
__device__ __align__(16) float g_wre[9 * NOC * NC];  // w reordered [tap][oc][c], tf32-rounded

// ---------------------------------------------------------------------------
// helpers
// ---------------------------------------------------------------------------
__device__ __forceinline__ uint32_t f2tf(float f) {
    uint32_t u;
    asm("cvt.rna.tf32.f32 %0, %1;" : "=r"(u) : "f"(f));
    return u;
}
__device__ __forceinline__ void mma_tf32(float* c, uint32_t a0, uint32_t a1,
                                         uint32_t a2, uint32_t a3,
                                         uint32_t b0, uint32_t b1) {
    asm volatile(
        "mma.sync.aligned.m16n8k8.row.col.f32.tf32.tf32.f32 "
        "{%0,%1,%2,%3}, {%4,%5,%6,%7}, {%8,%9}, {%0,%1,%2,%3};"
        : "+f"(c[0]), "+f"(c[1]), "+f"(c[2]), "+f"(c[3])
        : "r"(a0), "r"(a1), "r"(a2), "r"(a3), "r"(b0), "r"(b1));
}
__device__ __forceinline__ void cp_async4(void* smem_ptr, const void* gmem_ptr) {
    uint32_t s = (uint32_t)__cvta_generic_to_shared(smem_ptr);
    asm volatile("cp.async.ca.shared.global [%0], [%1], 4;" :: "r"(s), "l"(gmem_ptr));
}
__device__ __forceinline__ void cp_async16(void* smem_ptr, const void* gmem_ptr) {
    uint32_t s = (uint32_t)__cvta_generic_to_shared(smem_ptr);
    asm volatile("cp.async.cg.shared.global [%0], [%1], 16;" :: "r"(s), "l"(gmem_ptr));
}
__device__ __forceinline__ void cp_commit() { asm volatile("cp.async.commit_group;"); }
template <int N>
__device__ __forceinline__ void cp_wait() {
    asm volatile("cp.async.wait_group %0;" :: "n"(N));
}

// ---------------------------------------------------------------------------
// Kernel 1: per-pixel channel-parity sums
// ---------------------------------------------------------------------------
__global__ void parity_sum_kernel(const float* __restrict__ x) {
    int idx = blockIdx.x * blockDim.x + threadIdx.x;
    if (idx >= NB * HW) return;
    int b = idx / HW;
    int pix = idx - b * HW;
    const float* xp = x + (size_t)b * NC * HW + pix;
    float s0 = 0.f, s1 = 0.f;
#pragma unroll 8
    for (int c = 0; c < NC; c += 2) {
        s0 += xp[(size_t)c * HW];
        s1 += xp[(size_t)(c + 1) * HW];
    }
    g_T[(b * 2 + 0) * HW + pix] = s0;
    g_T[(b * 2 + 1) * HW + pix] = s1;
}

// ---------------------------------------------------------------------------
// Kernel 2: 3x3 edge-clamped box filter / 576 -> g_avg
// ---------------------------------------------------------------------------
__global__ void avg_kernel() {
    int idx = blockIdx.x * blockDim.x + threadIdx.x;
    if (idx >= NB * 2 * HW) return;
    int bu = idx / HW;
    int pix = idx - bu * HW;
    int i = pix / NW, j = pix - (pix / NW) * NW;
    const float* T = g_T + bu * HW;
    float s = 0.f;
#pragma unroll
    for (int r = -1; r <= 1; r++) {
        int y = min(max(i + r, 0), NH - 1);
#pragma unroll
        for (int q = -1; q <= 1; q++) {
            int xw = min(max(j + q, 0), NW - 1);
            s += T[y * NW + xw];
        }
    }
    g_avg[idx] = s * (1.0f / 576.0f);
}

// ---------------------------------------------------------------------------
// Kernel 3: W2[o,u] = sum_{c%2==u} sum_{r,s} w[o,c,r,s]   (fp32, original w)
// ---------------------------------------------------------------------------
__global__ void w2_kernel(const float* __restrict__ w) {
    __shared__ float s2[2];
    int o = blockIdx.x;
    int c = threadIdx.x;  // 0..127
    if (c < 2) s2[c] = 0.f;
    __syncthreads();
    const float* wp = w + ((size_t)o * NC + c) * 9;
    float s = 0.f;
#pragma unroll
    for (int k = 0; k < 9; k++) s += wp[k];
    atomicAdd(&s2[c & 1], s);
    __syncthreads();
    if (c < 2) g_W2[o * 2 + c] = s2[c];
}

// ---------------------------------------------------------------------------
// Kernel 3b: reorder weights -> g_wre[tap][oc][c], rounded to tf32
// ---------------------------------------------------------------------------
__global__ void wre_kernel(const float* __restrict__ w) {
    int idx = blockIdx.x * blockDim.x + threadIdx.x;
    if (idx >= NOC * NC * 9) return;
    int tap = idx % 9;
    int rem = idx / 9;          // oc*128 + c
    int oc = rem / NC;
    int c = rem - oc * NC;
    float v = w[((size_t)oc * NC + c) * 9 + tap];
    g_wre[(tap * NOC + oc) * NC + c] = __uint_as_float(f2tf(v));
}

// ---------------------------------------------------------------------------
// Kernel 4: implicit-GEMM conv via mma.sync tf32 + fused epilogue.
// CTA: 4 rows x 32 cols pixel tile (128 px), all 128 oc. 8 warps (4M x 2N).
// K loop: 4 c-chunks of 32 x 9 taps, cp.async double-buffered.
//
// k-permutation: mma k-slot l -> c=2l, slot l+4 -> c=2l+1, so A pairs
// (a0,a2),(a1,a3) and B pair (b0,b1) are contiguous LDS.64.
// x smem: [c2(16)][plane 456 floats = 6 rows x 76 (38 colpairs x 2)]
//   -> B pair-bank = 4l + g + const (conflict-free).
// w smem: [oc(128)][40 floats] -> A pair-bank = 4g + l + const (conflict-free).
// ---------------------------------------------------------------------------
constexpr int XPLANE = 456;                 // floats per c2 plane (228 pairs == 4 mod 16)
constexpr int XBUF = 16 * XPLANE;           // 7296 floats
constexpr int WROW = 40;                    // floats per oc row (20 pairs == 4 mod 16)
constexpr int WBUF = NOC * WROW;            // 5120 floats
constexpr int SMEM_FLOATS = 2 * XBUF + 2 * WBUF + NOC + 2 * NOC;
constexpr int SMEM_BYTES = SMEM_FLOATS * 4; // 100864 B

__global__ __launch_bounds__(256, 2) void conv_mma_kernel(
    const float* __restrict__ x, const float* __restrict__ bias,
    float* __restrict__ out) {
    extern __shared__ __align__(16) float smem[];
    float* xs = smem;                       // [2][XBUF]
    float* ws = smem + 2 * XBUF;            // [2][WBUF]
    float* s_bias = ws + 2 * WBUF;          // [128]
    float* s_w2 = s_bias + NOC;             // [256]

    int b = blockIdx.z;
    int col0 = (blockIdx.x & 1) * 32;
    int row0 = (blockIdx.x >> 1) * 4;

    int t = threadIdx.x;
    int wid = t >> 5, lane = t & 31;
    int g = lane >> 2, l = lane & 3;
    int wm = wid >> 1, wn = wid & 1;

    if (t < NOC) s_bias[t] = bias[t];
    if (t < 2 * NOC) s_w2[t] = g_W2[t];

    const float* xb = x + (size_t)b * NC * HW;

    // ---- async loaders ----
    auto load_x = [&](int cc, int buf) {
        float* dst = xs + buf * XBUF;
        const float* src = xb + (size_t)cc * 32 * HW;
#pragma unroll 1
        for (int e = t; e < 32 * 204; e += 256) {
            int c = e / 204;
            int rem = e - c * 204;
            int sr = rem / 34;
            int sc = rem - sr * 34;
            int gy = min(max(row0 - 1 + sr, 0), NH - 1);
            int gx = min(max(col0 - 1 + sc, 0), NW - 1);
            cp_async4(dst + (c >> 1) * XPLANE + sr * 76 + sc * 2 + (c & 1),
                      src + (size_t)c * HW + gy * NW + gx);
        }
    };
    auto load_w = [&](int cc, int tap, int buf) {
        float* dst = ws + buf * WBUF;
        const float* src = g_wre + (size_t)tap * NOC * NC + cc * 32;
#pragma unroll
        for (int e = t; e < NOC * 8; e += 256) {
            int oc = e >> 3;
            int q16 = e & 7;
            cp_async16(dst + oc * WROW + q16 * 4, src + oc * NC + q16 * 4);
        }
    };

    float acc[2][8][4];
#pragma unroll
    for (int mt = 0; mt < 2; mt++)
#pragma unroll
        for (int nt = 0; nt < 8; nt++)
#pragma unroll
            for (int k = 0; k < 4; k++) acc[mt][nt][k] = 0.f;

    load_x(0, 0);
    load_w(0, 0, 0);
    cp_commit();

#pragma unroll 1
    for (int step = 0; step < 36; step++) {
        int cc = step / 9;
        int tap = step - cc * 9;
        int nstep = step + 1;
        if (nstep < 36) {
            int ncc = nstep / 9;
            int ntap = nstep - ncc * 9;
            if (ntap == 0) load_x(ncc, ncc & 1);
            load_w(ncc, ntap, nstep & 1);
            cp_commit();
            cp_wait<1>();
        } else {
            cp_wait<0>();
        }
        __syncthreads();

        int r = tap / 3;           // col shift
        int sft = tap - r * 3;     // row shift
        // B base: c2 = l (+4q), pixel row = wn*2 + (nt>>2) + sft, col = (nt&3)*8 + g + r
        const float* Bbase = xs + (cc & 1) * XBUF + l * XPLANE +
                             (wn * 2 + sft) * 76 + (g + r) * 2;
        // A base: row = wm*32 + mt*16 + g (+8), c = 8q + 2l
        const float* Abase = ws + (step & 1) * WBUF + (wm * 32 + g) * WROW + 2 * l;

#pragma unroll
        for (int q = 0; q < 4; q++) {
            uint32_t A[2][4];
#pragma unroll
            for (int mt = 0; mt < 2; mt++) {
                float2 p0 = *(const float2*)(Abase + mt * (16 * WROW) + q * 8);
                float2 p1 = *(const float2*)(Abase + mt * (16 * WROW) + 8 * WROW + q * 8);
                A[mt][0] = __float_as_uint(p0.x);  // pre-rounded tf32
                A[mt][2] = __float_as_uint(p0.y);
                A[mt][1] = __float_as_uint(p1.x);
                A[mt][3] = __float_as_uint(p1.y);
            }
#pragma unroll
            for (int nt = 0; nt < 8; nt++) {
                float2 bp = *(const float2*)(Bbase + q * (4 * XPLANE) +
                                             (nt >> 2) * 76 + (nt & 3) * 16);
                uint32_t b0 = f2tf(bp.x);
                uint32_t b1 = f2tf(bp.y);
                mma_tf32(acc[0][nt], A[0][0], A[0][1], A[0][2], A[0][3], b0, b1);
                mma_tf32(acc[1][nt], A[1][0], A[1][1], A[1][2], A[1][3], b0, b1);
            }
        }
        __syncthreads();
    }

    // ---- epilogue: bias - W2*avg, leaky, + parity mean ----
    const float* avg0 = g_avg + (b * 2 + 0) * HW;
    const float* avg1 = g_avg + (b * 2 + 1) * HW;
#pragma unroll
    for (int nt = 0; nt < 8; nt++) {
        int i = row0 + wn * 2 + (nt >> 2);
        int j = col0 + (nt & 3) * 8 + 2 * l;
        float2 a0 = *(const float2*)(avg0 + i * NW + j);
        float2 a1 = *(const float2*)(avg1 + i * NW + j);
#pragma unroll
        for (int mt = 0; mt < 2; mt++) {
#pragma unroll
            for (int half = 0; half < 2; half++) {
                int o = wm * 32 + mt * 16 + half * 8 + g;
                float bw = s_bias[o];
                float w20 = s_w2[2 * o], w21 = s_w2[2 * o + 1];
                float v0 = acc[mt][nt][half * 2 + 0] + bw - w20 * a0.x - w21 * a1.x;
                float v1 = acc[mt][nt][half * 2 + 1] + bw - w20 * a0.y - w21 * a1.y;
                v0 = v0 > 0.f ? v0 : 0.01f * v0;
                v1 = v1 > 0.f ? v1 : 0.01f * v1;
                if (o & 1) { v0 += a1.x; v1 += a1.y; }
                else       { v0 += a0.x; v1 += a0.y; }
                float2 vv = make_float2(v0, v1);
                *(float2*)(out + ((size_t)(b * NOC + o)) * HW + i * NW + j) = vv;
            }
        }
    }
}

// ---------------------------------------------------------------------------
extern "C" void kernel_launch(void* const* d_in, const int* in_sizes, int n_in,
                              void* d_out, int out_size) {
    const float* x = (const float*)d_in[0];     // (16,128,64,64)
    const float* w = (const float*)d_in[1];     // (128,128,3,3)
    const float* bias = (const float*)d_in[2];  // (128,)
    float* out = (float*)d_out;                 // (16,128,64,64)

    cudaFuncSetAttribute(conv_mma_kernel,
                         cudaFuncAttributeMaxDynamicSharedMemorySize, SMEM_BYTES);

    parity_sum_kernel<<<(NB * HW + 255) / 256, 256>>>(x);
    avg_kernel<<<(NB * 2 * HW + 255) / 256, 256>>>();
    w2_kernel<<<NOC, 128>>>(w);
    wre_kernel<<<(NOC * NC * 9 + 255) / 256, 256>>>(w);

    dim3 grid(32, 1, NB);  // 32 pixel tiles (2x in x, 16 in y) x 16 batches
    conv_mma_kernel<<<grid, 256, SMEM_BYTES>>>(x, bias, out);
}

// round 15
// speedup vs baseline: 1.0007x; 1.0007x over previous
#include <cuda_runtime.h>
#include <cstdint>

// Problem constants
constexpr int NB = 16;
constexpr int NC = 128;
constexpr int NH = 64;
constexpr int NW = 64;
constexpr int HW = NH * NW;
constexpr int NOC = 128;

// Scratch (allocation-free rule: __device__ globals)
__device__ float g_T[NB * 2 * HW];        // per-parity channel sums
__device__ float g_avg[NB * 2 * HW];      // 3x3 box mean / 576
__device__ float g_W2[NOC * 2];           // sum of weights per (o, parity)
__device__ __align__(16) float g_wre[9 * NOC * NC];  // w reordered [tap][oc][c], tf32-rounded

// ---------------------------------------------------------------------------
// helpers
// ---------------------------------------------------------------------------
__device__ __forceinline__ uint32_t f2tf(float f) {
    uint32_t u;
    asm("cvt.rna.tf32.f32 %0, %1;" : "=r"(u) : "f"(f));
    return u;
}
__device__ __forceinline__ void mma_tf32(float* c, uint32_t a0, uint32_t a1,
                                         uint32_t a2, uint32_t a3,
                                         uint32_t b0, uint32_t b1) {
    asm volatile(
        "mma.sync.aligned.m16n8k8.row.col.f32.tf32.tf32.f32 "
        "{%0,%1,%2,%3}, {%4,%5,%6,%7}, {%8,%9}, {%0,%1,%2,%3};"
        : "+f"(c[0]), "+f"(c[1]), "+f"(c[2]), "+f"(c[3])
        : "r"(a0), "r"(a1), "r"(a2), "r"(a3), "r"(b0), "r"(b1));
}
__device__ __forceinline__ void cp_async4(void* smem_ptr, const void* gmem_ptr) {
    uint32_t s = (uint32_t)__cvta_generic_to_shared(smem_ptr);
    asm volatile("cp.async.ca.shared.global [%0], [%1], 4;" :: "r"(s), "l"(gmem_ptr));
}
__device__ __forceinline__ void cp_async16(void* smem_ptr, const void* gmem_ptr) {
    uint32_t s = (uint32_t)__cvta_generic_to_shared(smem_ptr);
    asm volatile("cp.async.cg.shared.global [%0], [%1], 16;" :: "r"(s), "l"(gmem_ptr));
}
__device__ __forceinline__ void cp_commit() { asm volatile("cp.async.commit_group;"); }
template <int N>
__device__ __forceinline__ void cp_wait() {
    asm volatile("cp.async.wait_group %0;" :: "n"(N));
}

// ---------------------------------------------------------------------------
// Kernel 1: per-pixel channel-parity sums
// ---------------------------------------------------------------------------
__global__ void parity_sum_kernel(const float* __restrict__ x) {
    int idx = blockIdx.x * blockDim.x + threadIdx.x;
    if (idx >= NB * HW) return;
    int b = idx / HW;
    int pix = idx - b * HW;
    const float* xp = x + (size_t)b * NC * HW + pix;
    float s0 = 0.f, s1 = 0.f;
#pragma unroll 8
    for (int c = 0; c < NC; c += 2) {
        s0 += xp[(size_t)c * HW];
        s1 += xp[(size_t)(c + 1) * HW];
    }
    g_T[(b * 2 + 0) * HW + pix] = s0;
    g_T[(b * 2 + 1) * HW + pix] = s1;
}

// ---------------------------------------------------------------------------
// Kernel 2: 3x3 edge-clamped box filter / 576 -> g_avg
// ---------------------------------------------------------------------------
__global__ void avg_kernel() {
    int idx = blockIdx.x * blockDim.x + threadIdx.x;
    if (idx >= NB * 2 * HW) return;
    int bu = idx / HW;
    int pix = idx - bu * HW;
    int i = pix / NW, j = pix - (pix / NW) * NW;
    const float* T = g_T + bu * HW;
    float s = 0.f;
#pragma unroll
    for (int r = -1; r <= 1; r++) {
        int y = min(max(i + r, 0), NH - 1);
#pragma unroll
        for (int q = -1; q <= 1; q++) {
            int xw = min(max(j + q, 0), NW - 1);
            s += T[y * NW + xw];
        }
    }
    g_avg[idx] = s * (1.0f / 576.0f);
}

// ---------------------------------------------------------------------------
// Kernel 3: W2[o,u] = sum_{c%2==u} sum_{r,s} w[o,c,r,s]   (fp32, original w)
// ---------------------------------------------------------------------------
__global__ void w2_kernel(const float* __restrict__ w) {
    __shared__ float s2[2];
    int o = blockIdx.x;
    int c = threadIdx.x;  // 0..127
    if (c < 2) s2[c] = 0.f;
    __syncthreads();
    const float* wp = w + ((size_t)o * NC + c) * 9;
    float s = 0.f;
#pragma unroll
    for (int k = 0; k < 9; k++) s += wp[k];
    atomicAdd(&s2[c & 1], s);
    __syncthreads();
    if (c < 2) g_W2[o * 2 + c] = s2[c];
}

// ---------------------------------------------------------------------------
// Kernel 3b: reorder weights -> g_wre[tap][oc][c], rounded to tf32
// ---------------------------------------------------------------------------
__global__ void wre_kernel(const float* __restrict__ w) {
    int idx = blockIdx.x * blockDim.x + threadIdx.x;
    if (idx >= NOC * NC * 9) return;
    int tap = idx % 9;
    int rem = idx / 9;          // oc*128 + c
    int oc = rem / NC;
    int c = rem - oc * NC;
    float v = w[((size_t)oc * NC + c) * 9 + tap];
    g_wre[(tap * NOC + oc) * NC + c] = __uint_as_float(f2tf(v));
}

// ---------------------------------------------------------------------------
// Kernel 4: implicit-GEMM conv via mma.sync tf32 + fused epilogue.
// CTA: 4 rows x 32 cols pixel tile (128 px), all 128 oc. 8 warps (4M x 2N).
// K loop: 4 c-chunks of 32 x 9 taps, cp.async double-buffered.
//
// k-permutation: mma k-slot l -> c=2l, slot l+4 -> c=2l+1, so A pairs
// (a0,a2),(a1,a3) and B pair (b0,b1) are contiguous LDS.64.
// x smem: [c2(16)][plane 456 floats = 6 rows x 76 (38 colpairs x 2)]
//   -> B pair-bank = 4l + g + const (conflict-free).
// w smem: [oc(128)][40 floats] -> A pair-bank = 4g + l + const (conflict-free).
// ---------------------------------------------------------------------------
constexpr int XPLANE = 456;                 // floats per c2 plane (228 pairs == 4 mod 16)
constexpr int XBUF = 16 * XPLANE;           // 7296 floats
constexpr int WROW = 40;                    // floats per oc row (20 pairs == 4 mod 16)
constexpr int WBUF = NOC * WROW;            // 5120 floats
constexpr int SMEM_FLOATS = 2 * XBUF + 2 * WBUF + NOC + 2 * NOC;
constexpr int SMEM_BYTES = SMEM_FLOATS * 4; // 100864 B

__global__ __launch_bounds__(256, 2) void conv_mma_kernel(
    const float* __restrict__ x, const float* __restrict__ bias,
    float* __restrict__ out) {
    extern __shared__ __align__(16) float smem[];
    float* xs = smem;                       // [2][XBUF]
    float* ws = smem + 2 * XBUF;            // [2][WBUF]
    float* s_bias = ws + 2 * WBUF;          // [128]
    float* s_w2 = s_bias + NOC;             // [256]

    int b = blockIdx.z;
    int col0 = (blockIdx.x & 1) * 32;
    int row0 = (blockIdx.x >> 1) * 4;

    int t = threadIdx.x;
    int wid = t >> 5, lane = t & 31;
    int g = lane >> 2, l = lane & 3;
    int wm = wid >> 1, wn = wid & 1;

    if (t < NOC) s_bias[t] = bias[t];
    if (t < 2 * NOC) s_w2[t] = g_W2[t];

    const float* xb = x + (size_t)b * NC * HW;

    // ---- async loaders ----
    auto load_x = [&](int cc, int buf) {
        float* dst = xs + buf * XBUF;
        const float* src = xb + (size_t)cc * 32 * HW;
#pragma unroll 1
        for (int e = t; e < 32 * 204; e += 256) {
            int c = e / 204;
            int rem = e - c * 204;
            int sr = rem / 34;
            int sc = rem - sr * 34;
            int gy = min(max(row0 - 1 + sr, 0), NH - 1);
            int gx = min(max(col0 - 1 + sc, 0), NW - 1);
            cp_async4(dst + (c >> 1) * XPLANE + sr * 76 + sc * 2 + (c & 1),
                      src + (size_t)c * HW + gy * NW + gx);
        }
    };
    auto load_w = [&](int cc, int tap, int buf) {
        float* dst = ws + buf * WBUF;
        const float* src = g_wre + (size_t)tap * NOC * NC + cc * 32;
#pragma unroll
        for (int e = t; e < NOC * 8; e += 256) {
            int oc = e >> 3;
            int q16 = e & 7;
            cp_async16(dst + oc * WROW + q16 * 4, src + oc * NC + q16 * 4);
        }
    };

    float acc[2][8][4];
#pragma unroll
    for (int mt = 0; mt < 2; mt++)
#pragma unroll
        for (int nt = 0; nt < 8; nt++)
#pragma unroll
            for (int k = 0; k < 4; k++) acc[mt][nt][k] = 0.f;

    load_x(0, 0);
    load_w(0, 0, 0);
    cp_commit();

#pragma unroll 1
    for (int step = 0; step < 36; step++) {
        int cc = step / 9;
        int tap = step - cc * 9;
        int nstep = step + 1;
        if (nstep < 36) {
            int ncc = nstep / 9;
            int ntap = nstep - ncc * 9;
            if (ntap == 0) load_x(ncc, ncc & 1);
            load_w(ncc, ntap, nstep & 1);
            cp_commit();
            cp_wait<1>();
        } else {
            cp_wait<0>();
        }
        __syncthreads();

        int r = tap / 3;           // col shift
        int sft = tap - r * 3;     // row shift
        // B base: c2 = l (+4q), pixel row = wn*2 + (nt>>2) + sft, col = (nt&3)*8 + g + r
        const float* Bbase = xs + (cc & 1) * XBUF + l * XPLANE +
                             (wn * 2 + sft) * 76 + (g + r) * 2;
        // A base: row = wm*32 + mt*16 + g (+8), c = 8q + 2l
        const float* Abase = ws + (step & 1) * WBUF + (wm * 32 + g) * WROW + 2 * l;

#pragma unroll
        for (int q = 0; q < 4; q++) {
            uint32_t A[2][4];
#pragma unroll
            for (int mt = 0; mt < 2; mt++) {
                float2 p0 = *(const float2*)(Abase + mt * (16 * WROW) + q * 8);
                float2 p1 = *(const float2*)(Abase + mt * (16 * WROW) + 8 * WROW + q * 8);
                A[mt][0] = __float_as_uint(p0.x);  // pre-rounded tf32
                A[mt][2] = __float_as_uint(p0.y);
                A[mt][1] = __float_as_uint(p1.x);
                A[mt][3] = __float_as_uint(p1.y);
            }
#pragma unroll
            for (int nt = 0; nt < 8; nt++) {
                float2 bp = *(const float2*)(Bbase + q * (4 * XPLANE) +
                                             (nt >> 2) * 76 + (nt & 3) * 16);
                uint32_t b0 = f2tf(bp.x);
                uint32_t b1 = f2tf(bp.y);
                mma_tf32(acc[0][nt], A[0][0], A[0][1], A[0][2], A[0][3], b0, b1);
                mma_tf32(acc[1][nt], A[1][0], A[1][1], A[1][2], A[1][3], b0, b1);
            }
        }
        __syncthreads();
    }

    // ---- epilogue: bias - W2*avg, leaky, + parity mean ----
    const float* avg0 = g_avg + (b * 2 + 0) * HW;
    const float* avg1 = g_avg + (b * 2 + 1) * HW;
#pragma unroll
    for (int nt = 0; nt < 8; nt++) {
        int i = row0 + wn * 2 + (nt >> 2);
        int j = col0 + (nt & 3) * 8 + 2 * l;
        float2 a0 = *(const float2*)(avg0 + i * NW + j);
        float2 a1 = *(const float2*)(avg1 + i * NW + j);
#pragma unroll
        for (int mt = 0; mt < 2; mt++) {
#pragma unroll
            for (int half = 0; half < 2; half++) {
                int o = wm * 32 + mt * 16 + half * 8 + g;
                float bw = s_bias[o];
                float w20 = s_w2[2 * o], w21 = s_w2[2 * o + 1];
                float v0 = acc[mt][nt][half * 2 + 0] + bw - w20 * a0.x - w21 * a1.x;
                float v1 = acc[mt][nt][half * 2 + 1] + bw - w20 * a0.y - w21 * a1.y;
                v0 = v0 > 0.f ? v0 : 0.01f * v0;
                v1 = v1 > 0.f ? v1 : 0.01f * v1;
                if (o & 1) { v0 += a1.x; v1 += a1.y; }
                else       { v0 += a0.x; v1 += a0.y; }
                float2 vv = make_float2(v0, v1);
                *(float2*)(out + ((size_t)(b * NOC + o)) * HW + i * NW + j) = vv;
            }
        }
    }
}

// ---------------------------------------------------------------------------
extern "C" void kernel_launch(void* const* d_in, const int* in_sizes, int n_in,
                              void* d_out, int out_size) {
    const float* x = (const float*)d_in[0];     // (16,128,64,64)
    const float* w = (const float*)d_in[1];     // (128,128,3,3)
    const float* bias = (const float*)d_in[2];  // (128,)
    float* out = (float*)d_out;                 // (16,128,64,64)

    cudaFuncSetAttribute(conv_mma_kernel,
                         cudaFuncAttributeMaxDynamicSharedMemorySize, SMEM_BYTES);

    parity_sum_kernel<<<(NB * HW + 255) / 256, 256>>>(x);
    avg_kernel<<<(NB * 2 * HW + 255) / 256, 256>>>();
    w2_kernel<<<NOC, 128>>>(w);
    wre_kernel<<<(NOC * NC * 9 + 255) / 256, 256>>>(w);

    dim3 grid(32, 1, NB);  // 32 pixel tiles (2x in x, 16 in y) x 16 batches
    conv_mma_kernel<<<grid, 256, SMEM_BYTES>>>(x, bias, out);
}

// round 17
// speedup vs baseline: 1.0443x; 1.0436x over previous
#include <cuda_runtime.h>
#include <cstdint>

// Problem constants
constexpr int NB = 16;
constexpr int NC = 128;
constexpr int NH = 64;
constexpr int NW = 64;
constexpr int HW = NH * NW;
constexpr int NOC = 128;

// Scratch (allocation-free rule: __device__ globals)
__device__ float g_T[NB * 2 * HW];        // per-parity channel sums
__device__ float g_avg[NB * 2 * HW];      // 3x3 box mean / 576
__device__ float g_W2[NOC * 2];           // sum of weights per (o, parity)
__device__ __align__(16) float g_wre[9 * NOC * NC];   // w reordered [tap][oc][c], tf32-rounded
__device__ __align__(16) float g_xtf[NB * NC * HW];   // x pre-rounded to tf32

// ---------------------------------------------------------------------------
// helpers
// ---------------------------------------------------------------------------
__device__ __forceinline__ uint32_t f2tf(float f) {
    uint32_t u;
    asm("cvt.rna.tf32.f32 %0, %1;" : "=r"(u) : "f"(f));
    return u;
}
__device__ __forceinline__ void mma_tf32(float* c, uint32_t a0, uint32_t a1,
                                         uint32_t a2, uint32_t a3,
                                         uint32_t b0, uint32_t b1) {
    asm volatile(
        "mma.sync.aligned.m16n8k8.row.col.f32.tf32.tf32.f32 "
        "{%0,%1,%2,%3}, {%4,%5,%6,%7}, {%8,%9}, {%0,%1,%2,%3};"
        : "+f"(c[0]), "+f"(c[1]), "+f"(c[2]), "+f"(c[3])
        : "r"(a0), "r"(a1), "r"(a2), "r"(a3), "r"(b0), "r"(b1));
}
__device__ __forceinline__ void cp_async4(void* smem_ptr, const void* gmem_ptr) {
    uint32_t s = (uint32_t)__cvta_generic_to_shared(smem_ptr);
    asm volatile("cp.async.ca.shared.global [%0], [%1], 4;" :: "r"(s), "l"(gmem_ptr));
}
__device__ __forceinline__ void cp_async16(void* smem_ptr, const void* gmem_ptr) {
    uint32_t s = (uint32_t)__cvta_generic_to_shared(smem_ptr);
    asm volatile("cp.async.cg.shared.global [%0], [%1], 16;" :: "r"(s), "l"(gmem_ptr));
}
__device__ __forceinline__ void cp_commit() { asm volatile("cp.async.commit_group;"); }
template <int N>
__device__ __forceinline__ void cp_wait() {
    asm volatile("cp.async.wait_group %0;" :: "n"(N));
}

// ---------------------------------------------------------------------------
// Kernel 1: per-pixel channel-parity sums (fp32) + tf32-rounded copy of x
// ---------------------------------------------------------------------------
__global__ void parity_sum_kernel(const float* __restrict__ x) {
    int idx = blockIdx.x * blockDim.x + threadIdx.x;
    if (idx >= NB * HW) return;
    int b = idx / HW;
    int pix = idx - b * HW;
    const float* xp = x + (size_t)b * NC * HW + pix;
    float* xo = g_xtf + (size_t)b * NC * HW + pix;
    float s0 = 0.f, s1 = 0.f;
#pragma unroll 8
    for (int c = 0; c < NC; c += 2) {
        float v0 = xp[(size_t)c * HW];
        float v1 = xp[(size_t)(c + 1) * HW];
        s0 += v0;
        s1 += v1;
        xo[(size_t)c * HW] = __uint_as_float(f2tf(v0));
        xo[(size_t)(c + 1) * HW] = __uint_as_float(f2tf(v1));
    }
    g_T[(b * 2 + 0) * HW + pix] = s0;
    g_T[(b * 2 + 1) * HW + pix] = s1;
}

// ---------------------------------------------------------------------------
// Kernel 2: 3x3 edge-clamped box filter / 576 -> g_avg
// ---------------------------------------------------------------------------
__global__ void avg_kernel() {
    int idx = blockIdx.x * blockDim.x + threadIdx.x;
    if (idx >= NB * 2 * HW) return;
    int bu = idx / HW;
    int pix = idx - bu * HW;
    int i = pix / NW, j = pix - (pix / NW) * NW;
    const float* T = g_T + bu * HW;
    float s = 0.f;
#pragma unroll
    for (int r = -1; r <= 1; r++) {
        int y = min(max(i + r, 0), NH - 1);
#pragma unroll
        for (int q = -1; q <= 1; q++) {
            int xw = min(max(j + q, 0), NW - 1);
            s += T[y * NW + xw];
        }
    }
    g_avg[idx] = s * (1.0f / 576.0f);
}

// ---------------------------------------------------------------------------
// Kernel 3: W2[o,u] = sum_{c%2==u} sum_{r,s} w[o,c,r,s]   (fp32, original w)
// ---------------------------------------------------------------------------
__global__ void w2_kernel(const float* __restrict__ w) {
    __shared__ float s2[2];
    int o = blockIdx.x;
    int c = threadIdx.x;  // 0..127
    if (c < 2) s2[c] = 0.f;
    __syncthreads();
    const float* wp = w + ((size_t)o * NC + c) * 9;
    float s = 0.f;
#pragma unroll
    for (int k = 0; k < 9; k++) s += wp[k];
    atomicAdd(&s2[c & 1], s);
    __syncthreads();
    if (c < 2) g_W2[o * 2 + c] = s2[c];
}

// ---------------------------------------------------------------------------
// Kernel 3b: reorder weights -> g_wre[tap][oc][c], rounded to tf32
// ---------------------------------------------------------------------------
__global__ void wre_kernel(const float* __restrict__ w) {
    int idx = blockIdx.x * blockDim.x + threadIdx.x;
    if (idx >= NOC * NC * 9) return;
    int tap = idx % 9;
    int rem = idx / 9;          // oc*128 + c
    int oc = rem / NC;
    int c = rem - oc * NC;
    float v = w[((size_t)oc * NC + c) * 9 + tap];
    g_wre[(tap * NOC + oc) * NC + c] = __uint_as_float(f2tf(v));
}

// ---------------------------------------------------------------------------
// Kernel 4: implicit-GEMM conv via mma.sync tf32 + fused epilogue.
// CTA: 4 rows x 32 cols pixel tile (128 px), all 128 oc. 8 warps (4M x 2N).
// K loop: 4 c-chunks of 32 x 9 taps, cp.async double-buffered.
// ONE __syncthreads per step: wait<0> -> sync -> prefetch(s+1) -> compute(s).
// x is pre-rounded tf32 (g_xtf) -> B fragments feed HMMA with no in-loop cvt.
//
// k-permutation: mma k-slot l -> c=2l, slot l+4 -> c=2l+1, so A pairs
// (a0,a2),(a1,a3) and B pair (b0,b1) are contiguous LDS.64.
// x smem: [c2(16)][plane 456 floats]  -> B pair-bank conflict-free.
// w smem: [oc(128)][40 floats]        -> A pair-bank conflict-free.
// ---------------------------------------------------------------------------
constexpr int XPLANE = 456;                 // floats per c2 plane (228 pairs == 4 mod 16)
constexpr int XBUF = 16 * XPLANE;           // 7296 floats
constexpr int WROW = 40;                    // floats per oc row (20 pairs == 4 mod 16)
constexpr int WBUF = NOC * WROW;            // 5120 floats
constexpr int SMEM_FLOATS = 2 * XBUF + 2 * WBUF + NOC + 2 * NOC;
constexpr int SMEM_BYTES = SMEM_FLOATS * 4; // 100864 B

__global__ __launch_bounds__(256, 2) void conv_mma_kernel(
    const float* __restrict__ bias, float* __restrict__ out) {
    extern __shared__ __align__(16) float smem[];
    float* xs = smem;                       // [2][XBUF]
    float* ws = smem + 2 * XBUF;            // [2][WBUF]
    float* s_bias = ws + 2 * WBUF;          // [128]
    float* s_w2 = s_bias + NOC;             // [256]

    int b = blockIdx.z;
    int col0 = (blockIdx.x & 1) * 32;
    int row0 = (blockIdx.x >> 1) * 4;

    int t = threadIdx.x;
    int wid = t >> 5, lane = t & 31;
    int g = lane >> 2, l = lane & 3;
    int wm = wid >> 1, wn = wid & 1;

    if (t < NOC) s_bias[t] = bias[t];
    if (t < 2 * NOC) s_w2[t] = g_W2[t];

    const float* xb = g_xtf + (size_t)b * NC * HW;

    // ---- async loaders ----
    auto load_x = [&](int cc, int buf) {
        float* dst = xs + buf * XBUF;
        const float* src = xb + (size_t)cc * 32 * HW;
#pragma unroll 1
        for (int e = t; e < 32 * 204; e += 256) {
            int c = e / 204;
            int rem = e - c * 204;
            int sr = rem / 34;
            int sc = rem - sr * 34;
            int gy = min(max(row0 - 1 + sr, 0), NH - 1);
            int gx = min(max(col0 - 1 + sc, 0), NW - 1);
            cp_async4(dst + (c >> 1) * XPLANE + sr * 76 + sc * 2 + (c & 1),
                      src + (size_t)c * HW + gy * NW + gx);
        }
    };
    auto load_w = [&](int cc, int tap, int buf) {
        float* dst = ws + buf * WBUF;
        const float* src = g_wre + (size_t)tap * NOC * NC + cc * 32;
#pragma unroll
        for (int e = t; e < NOC * 8; e += 256) {
            int oc = e >> 3;
            int q16 = e & 7;
            cp_async16(dst + oc * WROW + q16 * 4, src + oc * NC + q16 * 4);
        }
    };

    float acc[2][8][4];
#pragma unroll
    for (int mt = 0; mt < 2; mt++)
#pragma unroll
        for (int nt = 0; nt < 8; nt++)
#pragma unroll
            for (int k = 0; k < 4; k++) acc[mt][nt][k] = 0.f;

    load_x(0, 0);
    load_w(0, 0, 0);
    cp_commit();

#pragma unroll 1
    for (int step = 0; step < 36; step++) {
        int cc = step / 9;
        int tap = step - cc * 9;

        // Data for this step landed; also all warps are done reading the
        // buffers the next prefetch will overwrite.
        cp_wait<0>();
        __syncthreads();

        int nstep = step + 1;
        if (nstep < 36) {
            int ncc = nstep / 9;
            int ntap = nstep - ncc * 9;
            if (ntap == 0) load_x(ncc, ncc & 1);
            load_w(ncc, ntap, nstep & 1);
            cp_commit();
        }

        int r = tap / 3;           // col shift
        int sft = tap - r * 3;     // row shift
        const float* Bbase = xs + (cc & 1) * XBUF + l * XPLANE +
                             (wn * 2 + sft) * 76 + (g + r) * 2;
        const float* Abase = ws + (step & 1) * WBUF + (wm * 32 + g) * WROW + 2 * l;

#pragma unroll
        for (int q = 0; q < 4; q++) {
            uint32_t A[2][4];
#pragma unroll
            for (int mt = 0; mt < 2; mt++) {
                float2 p0 = *(const float2*)(Abase + mt * (16 * WROW) + q * 8);
                float2 p1 = *(const float2*)(Abase + mt * (16 * WROW) + 8 * WROW + q * 8);
                A[mt][0] = __float_as_uint(p0.x);  // pre-rounded tf32
                A[mt][2] = __float_as_uint(p0.y);
                A[mt][1] = __float_as_uint(p1.x);
                A[mt][3] = __float_as_uint(p1.y);
            }
#pragma unroll
            for (int nt = 0; nt < 8; nt++) {
                float2 bp = *(const float2*)(Bbase + q * (4 * XPLANE) +
                                             (nt >> 2) * 76 + (nt & 3) * 16);
                uint32_t b0 = __float_as_uint(bp.x);  // pre-rounded tf32
                uint32_t b1 = __float_as_uint(bp.y);
                mma_tf32(acc[0][nt], A[0][0], A[0][1], A[0][2], A[0][3], b0, b1);
                mma_tf32(acc[1][nt], A[1][0], A[1][1], A[1][2], A[1][3], b0, b1);
            }
        }
    }

    // ---- epilogue: bias - W2*avg, leaky, + parity mean ----
    const float* avg0 = g_avg + (b * 2 + 0) * HW;
    const float* avg1 = g_avg + (b * 2 + 1) * HW;
#pragma unroll
    for (int nt = 0; nt < 8; nt++) {
        int i = row0 + wn * 2 + (nt >> 2);
        int j = col0 + (nt & 3) * 8 + 2 * l;
        float2 a0 = *(const float2*)(avg0 + i * NW + j);
        float2 a1 = *(const float2*)(avg1 + i * NW + j);
#pragma unroll
        for (int mt = 0; mt < 2; mt++) {
#pragma unroll
            for (int half = 0; half < 2; half++) {
                int o = wm * 32 + mt * 16 + half * 8 + g;
                float bw = s_bias[o];
                float w20 = s_w2[2 * o], w21 = s_w2[2 * o + 1];
                float v0 = acc[mt][nt][half * 2 + 0] + bw - w20 * a0.x - w21 * a1.x;
                float v1 = acc[mt][nt][half * 2 + 1] + bw - w20 * a0.y - w21 * a1.y;
                v0 = v0 > 0.f ? v0 : 0.01f * v0;
                v1 = v1 > 0.f ? v1 : 0.01f * v1;
                if (o & 1) { v0 += a1.x; v1 += a1.y; }
                else       { v0 += a0.x; v1 += a0.y; }
                float2 vv = make_float2(v0, v1);
                *(float2*)(out + ((size_t)(b * NOC + o)) * HW + i * NW + j) = vv;
            }
        }
    }
}

// ---------------------------------------------------------------------------
extern "C" void kernel_launch(void* const* d_in, const int* in_sizes, int n_in,
                              void* d_out, int out_size) {
    const float* x = (const float*)d_in[0];     // (16,128,64,64)
    const float* w = (const float*)d_in[1];     // (128,128,3,3)
    const float* bias = (const float*)d_in[2];  // (128,)
    float* out = (float*)d_out;                 // (16,128,64,64)

    cudaFuncSetAttribute(conv_mma_kernel,
                         cudaFuncAttributeMaxDynamicSharedMemorySize, SMEM_BYTES);

    parity_sum_kernel<<<(NB * HW + 255) / 256, 256>>>(x);
    avg_kernel<<<(NB * 2 * HW + 255) / 256, 256>>>();
    w2_kernel<<<NOC, 128>>>(w);
    wre_kernel<<<(NOC * NC * 9 + 255) / 256, 256>>>(w);

    dim3 grid(32, 1, NB);  // 32 pixel tiles (2x in x, 16 in y) x 16 batches
    conv_mma_kernel<<<grid, 256, SMEM_BYTES>>>(bias, out);
}